// round 11
// baseline (speedup 1.0000x reference)
#include <cuda_runtime.h>
#include <math.h>
#include <stdint.h>

// ----------------------------------------------------------------------------
// NoiseRobustAttractorLayer — TF32 mma.sync. R11: k_head2 algebraically fused:
// dyn = h@(W2@D)+b2@D, sa = h@(W2@attrT)+b2@attrT  (composed weights
// precomputed) -> single K=256 GEMM with B=[W2|W2D] (+sa cols), no Ss
// round-trip, no phase-2 loop. K1/K2/K4/K5 = R10 verbatim (best: 1408us).
// ----------------------------------------------------------------------------

#define T_TOK 65536
#define EPSV  1e-5f

__device__ float g_xn  [(size_t)T_TOK * 512];   // fp32 (residual)
__device__ float g_xnt [(size_t)T_TOK * 512];   // tf32-rounded (GEMM A)
__device__ float g_gate[(size_t)T_TOK * 4];
__device__ float g_h   [(size_t)T_TOK * 1024];  // tf32-rounded
__device__ float g_comb[(size_t)T_TOK * 512];   // tf32-rounded
__device__ float g_oact[(size_t)T_TOK * 512];   // tf32-rounded

__device__ float g_hW1t[4 * 512 * 256];
__device__ float g_hW2t[4 * 256 * 128];
__device__ float g_oW1t[512 * 512];
__device__ float g_oW2t[512 * 512];

// composed weights (R11): W2@D, W2@attrT (tf32 bits), and their biases (fp32)
__device__ float g_hW2Dt[4 * 256 * 128];
__device__ float g_W2At [4 * 256 * 8];
__device__ float g_b2D  [4 * 128];
__device__ float g_b2A  [4 * 8];

__device__ __forceinline__ float warp_sum(float v) {
#pragma unroll
    for (int o = 16; o > 0; o >>= 1) v += __shfl_xor_sync(0xffffffffu, v, o);
    return v;
}
__device__ __forceinline__ float gelu_exact(float x) {
    return 0.5f * x * (1.0f + erff(x * 0.70710678118654752f));
}
__device__ __forceinline__ uint32_t f2tf(float x) {
    uint32_t r; asm("cvt.rna.tf32.f32 %0, %1;" : "=r"(r) : "f"(x)); return r;
}
__device__ __forceinline__ float f2tf_f(float x) {
    return __uint_as_float(f2tf(x));
}
__device__ __forceinline__ void mma_tf32(float c[4], const uint32_t a[4],
                                         uint32_t b0, uint32_t b1) {
    asm volatile(
        "mma.sync.aligned.m16n8k8.row.col.f32.tf32.tf32.f32 "
        "{%0,%1,%2,%3},{%4,%5,%6,%7},{%8,%9},{%0,%1,%2,%3};"
        : "+f"(c[0]), "+f"(c[1]), "+f"(c[2]), "+f"(c[3])
        : "r"(a[0]), "r"(a[1]), "r"(a[2]), "r"(a[3]), "r"(b0), "r"(b1));
}
__device__ __forceinline__ void cp16(void* s, const void* g) {
    uint32_t sa = (uint32_t)__cvta_generic_to_shared(s);
    asm volatile("cp.async.cg.shared.global [%0], [%1], 16;" :: "r"(sa), "l"(g));
}
#define CP_COMMIT()  asm volatile("cp.async.commit_group;")
#define CP_WAIT_2()  asm volatile("cp.async.wait_group 2;" ::: "memory")

// ============================================================================
// K0: weight pre-conversion fp32 -> tf32
// ============================================================================
__global__ void __launch_bounds__(256) k_prep(
    const float* __restrict__ hW1, const float* __restrict__ hW2,
    const float* __restrict__ oW1, const float* __restrict__ oW2)
{
    int i = blockIdx.x * 256 + threadIdx.x;
    if (i < 524288)       g_hW1t[i]          = f2tf_f(hW1[i]);
    else if (i < 655360)  g_hW2t[i - 524288] = f2tf_f(hW2[i - 524288]);
    else if (i < 917504)  g_oW1t[i - 655360] = f2tf_f(oW1[i - 655360]);
    else if (i < 1179648) g_oW2t[i - 917504] = f2tf_f(oW2[i - 917504]);
}

// ============================================================================
// K0b: composed weights  W2D = W2@D, W2A = W2@attrT, b2D = b2@D, b2A = b2@attrT
// per head = 32768 + 2048 + 128 + 8 = 34952 outputs; 4 heads.
// ============================================================================
__global__ void __launch_bounds__(256) k_prep2(
    const float* __restrict__ hW2, const float* __restrict__ dynm,
    const float* __restrict__ attr, const float* __restrict__ hb2)
{
    const int PER = 34952;
    int i = blockIdx.x * 256 + threadIdx.x;
    if (i >= 4 * PER) return;
    int h = i / PER, r = i % PER;
    const float* W2 = hW2 + (size_t)h * 256 * 128;
    const float* D  = dynm + (size_t)h * 128 * 128;
    const float* A  = attr + (size_t)h * 8 * 128;
    const float* b2 = hb2 + h * 128;
    if (r < 32768) {
        int k = r >> 7, j = r & 127;
        float s = 0.f;
        for (int d = 0; d < 128; d++) s += W2[k * 128 + d] * D[d * 128 + j];
        g_hW2Dt[(size_t)h * 32768 + k * 128 + j] = f2tf_f(s);
    } else if (r < 34816) {
        int rr = r - 32768; int k = rr >> 3, a = rr & 7;
        float s = 0.f;
        for (int d = 0; d < 128; d++) s += W2[k * 128 + d] * A[a * 128 + d];
        g_W2At[(size_t)h * 2048 + k * 8 + a] = f2tf_f(s);
    } else if (r < 34944) {
        int j = r - 34816;
        float s = 0.f;
        for (int d = 0; d < 128; d++) s += b2[d] * D[d * 128 + j];
        g_b2D[h * 128 + j] = s;
    } else {
        int a = r - 34944;
        float s = 0.f;
        for (int d = 0; d < 128; d++) s += b2[d] * A[a * 128 + d];
        g_b2A[h * 8 + a] = s;
    }
}

// ============================================================================
// K1: warp-per-token LN + gate (R10 verbatim).
// ============================================================================
__global__ void __launch_bounds__(256) k_ln_gate(
    const float* __restrict__ x, const float* __restrict__ ng,
    const float* __restrict__ nb, const float* __restrict__ gW,
    const float* __restrict__ gb)
{
    __shared__ float sgW[2048];
    __shared__ float sng[512], snb[512];
    const int tid = threadIdx.x;
    for (int i = tid; i < 2048; i += 256) sgW[i] = gW[i];
    for (int i = tid; i < 512; i += 256) { sng[i] = ng[i]; snb[i] = nb[i]; }
    __syncthreads();

    const int wid = tid >> 5, l = tid & 31;
    const float gb0 = gb[0], gb1 = gb[1], gb2 = gb[2], gb3 = gb[3];
    const float4* sgW4 = (const float4*)sgW;
    const float4* sng4 = (const float4*)sng;
    const float4* snb4 = (const float4*)snb;

    for (int t = blockIdx.x * 8 + wid; t < T_TOK; t += gridDim.x * 8) {
        const float4* xr = (const float4*)(x + (size_t)t * 512);
        float4 v[4];
#pragma unroll
        for (int j = 0; j < 4; j++) v[j] = xr[l + 32 * j];
        float s = 0.f;
#pragma unroll
        for (int j = 0; j < 4; j++) s += v[j].x + v[j].y + v[j].z + v[j].w;
        s = warp_sum(s);
        float m = s * (1.0f / 512.0f);
        float q = 0.f;
#pragma unroll
        for (int j = 0; j < 4; j++) {
            float dx = v[j].x - m, dy = v[j].y - m, dz = v[j].z - m, dw = v[j].w - m;
            q += dx * dx + dy * dy + dz * dz + dw * dw;
        }
        q = warp_sum(q);
        float rs = rsqrtf(q * (1.0f / 512.0f) + EPSV);

        float4 xnv[4];
        float4* xo  = (float4*)(g_xn  + (size_t)t * 512);
        float4* xot = (float4*)(g_xnt + (size_t)t * 512);
#pragma unroll
        for (int j = 0; j < 4; j++) {
            float4 gv = sng4[l + 32 * j];
            float4 bv = snb4[l + 32 * j];
            xnv[j].x = (v[j].x - m) * rs * gv.x + bv.x;
            xnv[j].y = (v[j].y - m) * rs * gv.y + bv.y;
            xnv[j].z = (v[j].z - m) * rs * gv.z + bv.z;
            xnv[j].w = (v[j].w - m) * rs * gv.w + bv.w;
            xo[l + 32 * j] = xnv[j];
            float4 tv;
            tv.x = f2tf_f(xnv[j].x); tv.y = f2tf_f(xnv[j].y);
            tv.z = f2tf_f(xnv[j].z); tv.w = f2tf_f(xnv[j].w);
            xot[l + 32 * j] = tv;
        }
        float p[4] = {0.f, 0.f, 0.f, 0.f};
#pragma unroll
        for (int h = 0; h < 4; h++) {
#pragma unroll
            for (int j = 0; j < 4; j++) {
                float4 wv = sgW4[h * 128 + l + 32 * j];
                p[h] += xnv[j].x * wv.x + xnv[j].y * wv.y
                      + xnv[j].z * wv.z + xnv[j].w * wv.w;
            }
            p[h] = warp_sum(p[h]);
        }
        if (l == 0) {
            g_gate[(size_t)t * 4 + 0] = 1.0f / (1.0f + expf(-(p[0] + gb0)));
            g_gate[(size_t)t * 4 + 1] = 1.0f / (1.0f + expf(-(p[1] + gb1)));
            g_gate[(size_t)t * 4 + 2] = 1.0f / (1.0f + expf(-(p[2] + gb2)));
            g_gate[(size_t)t * 4 + 3] = 1.0f / (1.0f + expf(-(p[3] + gb3)));
        }
    }
}

// ============================================================================
// K2: h = gelu(LN(xn @ hW1[h] + hb1)).  R10 verbatim (4-stage ring).
// ============================================================================
#define K2_SMEM 93184
__global__ void __launch_bounds__(256) k_head1_mma(
    const float* __restrict__ hb1,
    const float* __restrict__ hlg, const float* __restrict__ hlb)
{
    extern __shared__ __align__(16) char dsm[];
    uint32_t* As = (uint32_t*)dsm;                 // 20480 (4*64*20)
    uint32_t* Bs = (uint32_t*)(dsm + 20480);       // 67584 (4*16*264)
    float* sB  = (float*)(dsm + 88064);
    float* sG  = (float*)(dsm + 89088);
    float* sBt = (float*)(dsm + 90112);
    float* ps  = (float*)(dsm + 91136);            // 64*4
    float* pq  = (float*)(dsm + 92160);            // 64*4

    const int h = blockIdx.y;
    const int t0 = blockIdx.x * 64;
    const int tid = threadIdx.x, w = tid >> 5, l = tid & 31;
    const int wr = w >> 2, wc = w & 3, g = l >> 2, tig = l & 3;

    sB[tid] = hb1[h * 256 + tid]; sG[tid] = hlg[h * 256 + tid]; sBt[tid] = hlb[h * 256 + tid];

    float acc[2][8][4];
#pragma unroll
    for (int mt = 0; mt < 2; mt++)
#pragma unroll
        for (int nt = 0; nt < 8; nt++)
#pragma unroll
            for (int i = 0; i < 4; i++) acc[mt][nt][i] = 0.f;

    const float* Wp = g_hW1t + (size_t)h * 512 * 256;
    const int ar = tid >> 2, ac4 = (tid & 3) * 4;
    const float* Ap = g_xnt + (size_t)(t0 + ar) * 512 + ac4;

    auto load_stage = [&](int s, int k0) {
        cp16(&As[s * 1280 + ar * 20 + ac4], Ap + k0);
#pragma unroll
        for (int i = 0; i < 4; i++) {
            int idx = tid + 256 * i;
            int kk = idx >> 6, c4 = (idx & 63) * 4;
            cp16(&Bs[s * 4224 + kk * 264 + c4], Wp + (size_t)(k0 + kk) * 256 + c4);
        }
    };

    load_stage(0, 0);  CP_COMMIT();
    load_stage(1, 16); CP_COMMIT();
    load_stage(2, 32); CP_COMMIT();
    int cur = 0;
    for (int it = 0; it < 32; it++) {
        CP_WAIT_2();
        __syncthreads();
        if (it + 3 < 32) load_stage((cur + 3) & 3, (it + 3) * 16);
        CP_COMMIT();
        const uint32_t* Ab = &As[cur * 1280];
        const uint32_t* Bb = &Bs[cur * 4224];
#pragma unroll
        for (int ks = 0; ks < 16; ks += 8) {
            uint32_t af[2][4];
#pragma unroll
            for (int mt = 0; mt < 2; mt++) {
                int rb = (wr * 32 + mt * 16 + g) * 20 + ks;
                af[mt][0] = Ab[rb + tig];       af[mt][1] = Ab[rb + 160 + tig];
                af[mt][2] = Ab[rb + tig + 4];   af[mt][3] = Ab[rb + 160 + tig + 4];
            }
#pragma unroll
            for (int nt = 0; nt < 8; nt++) {
                int cb = wc * 64 + nt * 8 + g;
                uint32_t b0 = Bb[(ks + tig) * 264 + cb];
                uint32_t b1 = Bb[(ks + tig + 4) * 264 + cb];
                mma_tf32(acc[0][nt], af[0], b0, b1);
                mma_tf32(acc[1][nt], af[1], b0, b1);
            }
        }
        cur = (cur + 1) & 3;
    }
    __syncthreads();

    float rsm[4] = {0, 0, 0, 0}, rsq[4] = {0, 0, 0, 0};
#pragma unroll
    for (int mt = 0; mt < 2; mt++)
#pragma unroll
        for (int nt = 0; nt < 8; nt++) {
            int c0 = wc * 64 + nt * 8 + 2 * tig;
            float v0 = acc[mt][nt][0] + sB[c0], v1 = acc[mt][nt][1] + sB[c0 + 1];
            float v2 = acc[mt][nt][2] + sB[c0], v3 = acc[mt][nt][3] + sB[c0 + 1];
            acc[mt][nt][0] = v0; acc[mt][nt][1] = v1; acc[mt][nt][2] = v2; acc[mt][nt][3] = v3;
            rsm[mt * 2 + 0] += v0 + v1; rsq[mt * 2 + 0] += v0 * v0 + v1 * v1;
            rsm[mt * 2 + 1] += v2 + v3; rsq[mt * 2 + 1] += v2 * v2 + v3 * v3;
        }
#pragma unroll
    for (int off = 1; off < 4; off <<= 1)
#pragma unroll
        for (int q = 0; q < 4; q++) {
            rsm[q] += __shfl_xor_sync(0xffffffffu, rsm[q], off);
            rsq[q] += __shfl_xor_sync(0xffffffffu, rsq[q], off);
        }
    if (tig == 0) {
#pragma unroll
        for (int q = 0; q < 4; q++) {
            int row = wr * 32 + (q >> 1) * 16 + (q & 1) * 8 + g;
            ps[row * 4 + wc] = rsm[q]; pq[row * 4 + wc] = rsq[q];
        }
    }
    __syncthreads();
    float mv[4], rv[4];
#pragma unroll
    for (int q = 0; q < 4; q++) {
        int row = wr * 32 + (q >> 1) * 16 + (q & 1) * 8 + g;
        float s  = ps[row * 4 + 0] + ps[row * 4 + 1] + ps[row * 4 + 2] + ps[row * 4 + 3];
        float s2 = pq[row * 4 + 0] + pq[row * 4 + 1] + pq[row * 4 + 2] + pq[row * 4 + 3];
        float m = s * (1.f / 256.f);
        float var = s2 * (1.f / 256.f) - m * m;
        mv[q] = m; rv[q] = rsqrtf(var + EPSV);
    }
#pragma unroll
    for (int mt = 0; mt < 2; mt++)
#pragma unroll
        for (int nt = 0; nt < 8; nt++) {
            int c0 = wc * 64 + nt * 8 + 2 * tig;
            int q0 = mt * 2;
            int row0 = t0 + wr * 32 + mt * 16 + g;
            float u0 = gelu_exact((acc[mt][nt][0] - mv[q0]) * rv[q0] * sG[c0] + sBt[c0]);
            float u1 = gelu_exact((acc[mt][nt][1] - mv[q0]) * rv[q0] * sG[c0 + 1] + sBt[c0 + 1]);
            *(float2*)&g_h[(size_t)row0 * 1024 + h * 256 + c0] =
                make_float2(f2tf_f(u0), f2tf_f(u1));
            float u2 = gelu_exact((acc[mt][nt][2] - mv[q0 + 1]) * rv[q0 + 1] * sG[c0] + sBt[c0]);
            float u3 = gelu_exact((acc[mt][nt][3] - mv[q0 + 1]) * rv[q0 + 1] * sG[c0 + 1] + sBt[c0 + 1]);
            *(float2*)&g_h[(size_t)(row0 + 8) * 1024 + h * 256 + c0] =
                make_float2(f2tf_f(u2), f2tf_f(u3));
        }
}

// ============================================================================
// K3 (R11): ONE GEMM pass. B = [W2 | W2@D] (N=256) + sa cols via W2@attrT.
// block 256 (warps 2x4), BM=64, K=256, 4-stage ring. Each warp holds state
// AND dyn for the same columns -> register-local mix. No Ss buffer.
// smem: As 20480 | Bs 67584 | WA 8192 | At 4096 | Sa 2048 | Sw 2048 |
//       s2p 1024 | a2s 32 | Sgt 256 | sb2 512 | sbD 512 | sbA 32 = 106816
// ============================================================================
#define K3_SMEM 106816
__global__ void __launch_bounds__(256, 2) k_head2_mma(
    const float* __restrict__ hb2, const float* __restrict__ attr)
{
    extern __shared__ __align__(16) char dsm[];
    uint32_t* As  = (uint32_t*)dsm;                // 20480 (4*64*20)
    uint32_t* Bs  = (uint32_t*)(dsm + 20480);      // 67584 (4*16*264)
    uint32_t* WA  = (uint32_t*)(dsm + 88064);      //  8192 (256*8)
    float*    At  = (float*)(dsm + 96256);         //  4096 (8*128)
    float*    Sa  = (float*)(dsm + 100352);        //  2048 (64*8)
    float*    Sw  = (float*)(dsm + 102400);        //  2048
    float*    s2p = (float*)(dsm + 104448);        //  1024 (64*4)
    float*    a2s = (float*)(dsm + 105472);        //    32
    float*    Sgt = (float*)(dsm + 105504);        //   256
    float*    sb2 = (float*)(dsm + 105760);        //   512
    float*    sbD = (float*)(dsm + 106272);        //   512
    float*    sbA = (float*)(dsm + 106784);        //    32

    const int h = blockIdx.y;
    const int t0 = blockIdx.x * 64;
    const int tid = threadIdx.x, w = tid >> 5, l = tid & 31;
    const int wr = w >> 2, wc = w & 3, g = l >> 2, tig = l & 3;

    // preload small tables (plain stores; first mainloop barrier publishes them)
    *(float4*)&At[tid * 4] = *(const float4*)(attr + (size_t)h * 1024 + tid * 4);
    {
        const float4* wa = (const float4*)(g_W2At + (size_t)h * 2048);
#pragma unroll
        for (int i = 0; i < 2; i++)
            ((float4*)WA)[tid + 256 * i] = wa[tid + 256 * i];
    }
    if (tid < 128) { sb2[tid] = hb2[h * 128 + tid]; sbD[tid] = g_b2D[h * 128 + tid]; }
    else if (tid < 136) sbA[tid - 128] = g_b2A[h * 8 + (tid - 128)];

    float accS[2][4][4], accD[2][4][4], scc[2][4];
#pragma unroll
    for (int mt = 0; mt < 2; mt++) {
#pragma unroll
        for (int nt = 0; nt < 4; nt++)
#pragma unroll
            for (int i = 0; i < 4; i++) { accS[mt][nt][i] = 0.f; accD[mt][nt][i] = 0.f; }
#pragma unroll
        for (int i = 0; i < 4; i++) scc[mt][i] = 0.f;
    }

    const int ar = tid >> 2, ac4 = (tid & 3) * 4;
    const float* Ap  = g_h + (size_t)(t0 + ar) * 1024 + h * 256 + ac4;
    const float* Wp2 = g_hW2t  + (size_t)h * 256 * 128;
    const float* WpD = g_hW2Dt + (size_t)h * 256 * 128;

    auto load_stage = [&](int s, int k0) {
        cp16(&As[s * 1280 + ar * 20 + ac4], Ap + k0);
#pragma unroll
        for (int i = 0; i < 4; i++) {
            int idx = tid + 256 * i;
            int kk = idx >> 6, c4 = (idx & 63) * 4;
            const float* src = (c4 < 128)
                ? (Wp2 + (size_t)(k0 + kk) * 128 + c4)
                : (WpD + (size_t)(k0 + kk) * 128 + (c4 - 128));
            cp16(&Bs[s * 4224 + kk * 264 + c4], src);
        }
    };

    load_stage(0, 0);  CP_COMMIT();
    load_stage(1, 16); CP_COMMIT();
    load_stage(2, 32); CP_COMMIT();
    int cur = 0;
    for (int it = 0; it < 16; it++) {
        CP_WAIT_2();
        __syncthreads();
        if (it + 3 < 16) load_stage((cur + 3) & 3, (it + 3) * 16);
        CP_COMMIT();
        const uint32_t* Ab = &As[cur * 1280];
        const uint32_t* Bb = &Bs[cur * 4224];
        const int kbase = it * 16;
#pragma unroll
        for (int ks = 0; ks < 16; ks += 8) {
            uint32_t af[2][4];
#pragma unroll
            for (int mt = 0; mt < 2; mt++) {
                int rb = (wr * 32 + mt * 16 + g) * 20 + ks;
                af[mt][0] = Ab[rb + tig];       af[mt][1] = Ab[rb + 160 + tig];
                af[mt][2] = Ab[rb + tig + 4];   af[mt][3] = Ab[rb + 160 + tig + 4];
            }
#pragma unroll
            for (int nt = 0; nt < 4; nt++) {
                int cb = wc * 32 + nt * 8 + g;
                uint32_t b0 = Bb[(ks + tig) * 264 + cb];
                uint32_t b1 = Bb[(ks + tig + 4) * 264 + cb];
                mma_tf32(accS[0][nt], af[0], b0, b1);
                mma_tf32(accS[1][nt], af[1], b0, b1);
            }
#pragma unroll
            for (int nt = 0; nt < 4; nt++) {
                int cb = 128 + wc * 32 + nt * 8 + g;
                uint32_t b0 = Bb[(ks + tig) * 264 + cb];
                uint32_t b1 = Bb[(ks + tig + 4) * 264 + cb];
                mma_tf32(accD[0][nt], af[0], b0, b1);
                mma_tf32(accD[1][nt], af[1], b0, b1);
            }
            uint32_t b0s = WA[(kbase + ks + tig) * 8 + g];
            uint32_t b1s = WA[(kbase + ks + tig + 4) * 8 + g];
            mma_tf32(scc[0], af[0], b0s, b1s);
            mma_tf32(scc[1], af[1], b0s, b1s);
        }
        cur = (cur + 1) & 3;
    }
    __syncthreads();

    if (tid < 8) {
        float q = 0.f;
#pragma unroll
        for (int k = 0; k < 128; k++) q += At[tid * 128 + k] * At[tid * 128 + k];
        a2s[tid] = q;
    }

    // bias add for state + ||s||^2 partials
    {
        float rq[4] = {0, 0, 0, 0};
#pragma unroll
        for (int mt = 0; mt < 2; mt++)
#pragma unroll
            for (int nt = 0; nt < 4; nt++) {
                int c0 = wc * 32 + nt * 8 + 2 * tig;
                float b0v = sb2[c0], b1v = sb2[c0 + 1];
                float v0 = accS[mt][nt][0] + b0v;
                float v1 = accS[mt][nt][1] + b1v;
                float v2 = accS[mt][nt][2] + b0v;
                float v3 = accS[mt][nt][3] + b1v;
                accS[mt][nt][0] = v0; accS[mt][nt][1] = v1;
                accS[mt][nt][2] = v2; accS[mt][nt][3] = v3;
                rq[mt * 2 + 0] += v0 * v0 + v1 * v1;
                rq[mt * 2 + 1] += v2 * v2 + v3 * v3;
            }
#pragma unroll
        for (int off = 1; off < 4; off <<= 1)
#pragma unroll
            for (int q = 0; q < 4; q++)
                rq[q] += __shfl_xor_sync(0xffffffffu, rq[q], off);
        if (tig == 0) {
#pragma unroll
            for (int q = 0; q < 4; q++) {
                int row = wr * 32 + (q >> 1) * 16 + (q & 1) * 8 + g;
                s2p[row * 4 + wc] = rq[q];
            }
        }
    }
    if (wc == 0) {
#pragma unroll
        for (int mt = 0; mt < 2; mt++) {
            int row = wr * 32 + mt * 16 + g;
            Sa[row * 8 + 2 * tig]           = scc[mt][0];
            Sa[row * 8 + 2 * tig + 1]       = scc[mt][1];
            Sa[(row + 8) * 8 + 2 * tig]     = scc[mt][2];
            Sa[(row + 8) * 8 + 2 * tig + 1] = scc[mt][3];
        }
    }
    __syncthreads();

    const float invs = 0.08838834764831845f;  // 1/sqrt(128)
    if (tid < 64) {
        int row = tid;
        float s2 = s2p[row * 4 + 0] + s2p[row * 4 + 1] + s2p[row * 4 + 2] + s2p[row * 4 + 3];
        float lgt[8], mx = -1e30f;
#pragma unroll
        for (int a = 0; a < 8; a++) {
            float sa = Sa[row * 8 + a] + sbA[a];
            float dd = sqrtf(fmaxf(s2 + a2s[a] - 2.0f * sa, 0.0f));
            lgt[a] = -dd * invs;
            mx = fmaxf(mx, lgt[a]);
        }
        float e[8], se = 0.f;
#pragma unroll
        for (int a = 0; a < 8; a++) { e[a] = expf(lgt[a] - mx); se += e[a]; }
        float ise = 1.0f / se;
#pragma unroll
        for (int a = 0; a < 8; a++) Sw[row * 8 + a] = e[a] * ise;
        Sgt[row] = 0.1f * g_gate[(size_t)(t0 + row) * 4 + h];
    }
    __syncthreads();

    // register-local mix
#pragma unroll
    for (int mt = 0; mt < 2; mt++)
#pragma unroll
        for (int nt = 0; nt < 4; nt++) {
            int c0 = wc * 32 + nt * 8 + 2 * tig;
            float bD0 = sbD[c0], bD1 = sbD[c0 + 1];
#pragma unroll
            for (int half = 0; half < 2; half++) {
                int row = wr * 32 + mt * 16 + g + 8 * half;
                float gt = Sgt[row];
                float sv0 = accS[mt][nt][2 * half + 0];
                float sv1 = accS[mt][nt][2 * half + 1];
                float dv0 = accD[mt][nt][2 * half + 0] + bD0;
                float dv1 = accD[mt][nt][2 * half + 1] + bD1;
                float ai0 = 0.f, ai1 = 0.f;
#pragma unroll
                for (int a = 0; a < 8; a++) {
                    float wgt = Sw[row * 8 + a];
                    ai0 += wgt * At[a * 128 + c0];
                    ai1 += wgt * At[a * 128 + c0 + 1];
                }
                float o0 = f2tf_f(sv0 + gt * (ai0 - sv0 + tanhf(dv0)));
                float o1 = f2tf_f(sv1 + gt * (ai1 - sv1 + tanhf(dv1)));
                *(float2*)&g_comb[(size_t)(t0 + row) * 512 + h * 128 + c0] =
                    make_float2(o0, o1);
            }
        }
}

// ============================================================================
// K4: o1 = gelu(LN(comb @ oW1 + ob1)).  R10 verbatim (4-stage ring).
// ============================================================================
#define K4_SMEM 163840
__global__ void __launch_bounds__(512) k_out1_mma(
    const float* __restrict__ ob1,
    const float* __restrict__ olg, const float* __restrict__ olb)
{
    extern __shared__ __align__(16) char dsm[];
    uint32_t* As = (uint32_t*)dsm;                 // 20480 (4*64*20)
    uint32_t* Bs = (uint32_t*)(dsm + 20480);       // 133120 (4*16*520)
    float* sB  = (float*)(dsm + 153600);
    float* sG  = (float*)(dsm + 155648);
    float* sBt = (float*)(dsm + 157696);
    float* ps  = (float*)(dsm + 159744);           // 64*8
    float* pq  = (float*)(dsm + 161792);

    const int t0 = blockIdx.x * 64;
    const int tid = threadIdx.x, w = tid >> 5, l = tid & 31;
    const int wr = w >> 3, wc = w & 7, g = l >> 2, tig = l & 3;

    sB[tid] = ob1[tid]; sG[tid] = olg[tid]; sBt[tid] = olb[tid];

    float acc[2][8][4];
#pragma unroll
    for (int mt = 0; mt < 2; mt++)
#pragma unroll
        for (int nt = 0; nt < 8; nt++)
#pragma unroll
            for (int i = 0; i < 4; i++) acc[mt][nt][i] = 0.f;

    const int ar = tid >> 2, ac4 = (tid & 3) * 4;
    const float* Ap = g_comb + (size_t)(t0 + (ar & 63)) * 512 + ac4;

    auto load_stage = [&](int s, int k0) {
        if (tid < 256) cp16(&As[s * 1280 + ar * 20 + ac4], Ap + k0);
#pragma unroll
        for (int i = 0; i < 4; i++) {
            int idx = tid + 512 * i;
            int kk = idx >> 7, c4 = (idx & 127) * 4;
            cp16(&Bs[s * 8320 + kk * 520 + c4], g_oW1t + (size_t)(k0 + kk) * 512 + c4);
        }
    };

    load_stage(0, 0);  CP_COMMIT();
    load_stage(1, 16); CP_COMMIT();
    load_stage(2, 32); CP_COMMIT();
    int cur = 0;
    for (int it = 0; it < 32; it++) {
        CP_WAIT_2();
        __syncthreads();
        if (it + 3 < 32) load_stage((cur + 3) & 3, (it + 3) * 16);
        CP_COMMIT();
        const uint32_t* Ab = &As[cur * 1280];
        const uint32_t* Bb = &Bs[cur * 8320];
#pragma unroll
        for (int ks = 0; ks < 16; ks += 8) {
            uint32_t af[2][4];
#pragma unroll
            for (int mt = 0; mt < 2; mt++) {
                int rb = (wr * 32 + mt * 16 + g) * 20 + ks;
                af[mt][0] = Ab[rb + tig];       af[mt][1] = Ab[rb + 160 + tig];
                af[mt][2] = Ab[rb + tig + 4];   af[mt][3] = Ab[rb + 160 + tig + 4];
            }
#pragma unroll
            for (int nt = 0; nt < 8; nt++) {
                int cb = wc * 64 + nt * 8 + g;
                uint32_t b0 = Bb[(ks + tig) * 520 + cb];
                uint32_t b1 = Bb[(ks + tig + 4) * 520 + cb];
                mma_tf32(acc[0][nt], af[0], b0, b1);
                mma_tf32(acc[1][nt], af[1], b0, b1);
            }
        }
        cur = (cur + 1) & 3;
    }
    __syncthreads();

    float rsm[4] = {0, 0, 0, 0}, rsq[4] = {0, 0, 0, 0};
#pragma unroll
    for (int mt = 0; mt < 2; mt++)
#pragma unroll
        for (int nt = 0; nt < 8; nt++) {
            int c0 = wc * 64 + nt * 8 + 2 * tig;
            float v0 = acc[mt][nt][0] + sB[c0], v1 = acc[mt][nt][1] + sB[c0 + 1];
            float v2 = acc[mt][nt][2] + sB[c0], v3 = acc[mt][nt][3] + sB[c0 + 1];
            acc[mt][nt][0] = v0; acc[mt][nt][1] = v1; acc[mt][nt][2] = v2; acc[mt][nt][3] = v3;
            rsm[mt * 2 + 0] += v0 + v1; rsq[mt * 2 + 0] += v0 * v0 + v1 * v1;
            rsm[mt * 2 + 1] += v2 + v3; rsq[mt * 2 + 1] += v2 * v2 + v3 * v3;
        }
#pragma unroll
    for (int off = 1; off < 4; off <<= 1)
#pragma unroll
        for (int q = 0; q < 4; q++) {
            rsm[q] += __shfl_xor_sync(0xffffffffu, rsm[q], off);
            rsq[q] += __shfl_xor_sync(0xffffffffu, rsq[q], off);
        }
    if (tig == 0) {
#pragma unroll
        for (int q = 0; q < 4; q++) {
            int row = wr * 32 + (q >> 1) * 16 + (q & 1) * 8 + g;
            ps[row * 8 + wc] = rsm[q]; pq[row * 8 + wc] = rsq[q];
        }
    }
    __syncthreads();
    float mv[4], rv[4];
#pragma unroll
    for (int q = 0; q < 4; q++) {
        int row = wr * 32 + (q >> 1) * 16 + (q & 1) * 8 + g;
        float s = 0.f, s2 = 0.f;
#pragma unroll
        for (int j = 0; j < 8; j++) { s += ps[row * 8 + j]; s2 += pq[row * 8 + j]; }
        float m = s * (1.f / 512.f);
        float var = s2 * (1.f / 512.f) - m * m;
        mv[q] = m; rv[q] = rsqrtf(var + EPSV);
    }
#pragma unroll
    for (int mt = 0; mt < 2; mt++)
#pragma unroll
        for (int nt = 0; nt < 8; nt++) {
            int c0 = wc * 64 + nt * 8 + 2 * tig;
            int q0 = mt * 2;
            int row0 = t0 + wr * 32 + mt * 16 + g;
            float u0 = gelu_exact((acc[mt][nt][0] - mv[q0]) * rv[q0] * sG[c0] + sBt[c0]);
            float u1 = gelu_exact((acc[mt][nt][1] - mv[q0]) * rv[q0] * sG[c0 + 1] + sBt[c0 + 1]);
            *(float2*)&g_oact[(size_t)row0 * 512 + c0] = make_float2(f2tf_f(u0), f2tf_f(u1));
            float u2 = gelu_exact((acc[mt][nt][2] - mv[q0 + 1]) * rv[q0 + 1] * sG[c0] + sBt[c0]);
            float u3 = gelu_exact((acc[mt][nt][3] - mv[q0 + 1]) * rv[q0 + 1] * sG[c0 + 1] + sBt[c0 + 1]);
            *(float2*)&g_oact[(size_t)(row0 + 8) * 512 + c0] = make_float2(f2tf_f(u2), f2tf_f(u3));
        }
}

// ============================================================================
// K5: out = xn + oact @ oW2 + ob2.  R10 verbatim (4-stage ring).
// ============================================================================
#define K5_SMEM 155648
__global__ void __launch_bounds__(512) k_out2_mma(
    const float* __restrict__ ob2, float* __restrict__ out)
{
    extern __shared__ __align__(16) char dsm[];
    uint32_t* As = (uint32_t*)dsm;                 // 20480
    uint32_t* Bs = (uint32_t*)(dsm + 20480);       // 133120
    float* sB = (float*)(dsm + 153600);

    const int t0 = blockIdx.x * 64;
    const int tid = threadIdx.x, w = tid >> 5, l = tid & 31;
    const int wr = w >> 3, wc = w & 7, g = l >> 2, tig = l & 3;

    sB[tid] = ob2[tid];

    float acc[2][8][4];
#pragma unroll
    for (int mt = 0; mt < 2; mt++)
#pragma unroll
        for (int nt = 0; nt < 8; nt++)
#pragma unroll
            for (int i = 0; i < 4; i++) acc[mt][nt][i] = 0.f;

    const int ar = tid >> 2, ac4 = (tid & 3) * 4;
    const float* Ap = g_oact + (size_t)(t0 + (ar & 63)) * 512 + ac4;

    auto load_stage = [&](int s, int k0) {
        if (tid < 256) cp16(&As[s * 1280 + ar * 20 + ac4], Ap + k0);
#pragma unroll
        for (int i = 0; i < 4; i++) {
            int idx = tid + 512 * i;
            int kk = idx >> 7, c4 = (idx & 127) * 4;
            cp16(&Bs[s * 8320 + kk * 520 + c4], g_oW2t + (size_t)(k0 + kk) * 512 + c4);
        }
    };

    load_stage(0, 0);  CP_COMMIT();
    load_stage(1, 16); CP_COMMIT();
    load_stage(2, 32); CP_COMMIT();
    int cur = 0;
    for (int it = 0; it < 32; it++) {
        CP_WAIT_2();
        __syncthreads();
        if (it + 3 < 32) load_stage((cur + 3) & 3, (it + 3) * 16);
        CP_COMMIT();
        const uint32_t* Ab = &As[cur * 1280];
        const uint32_t* Bb = &Bs[cur * 8320];
#pragma unroll
        for (int ks = 0; ks < 16; ks += 8) {
            uint32_t af[2][4];
#pragma unroll
            for (int mt = 0; mt < 2; mt++) {
                int rb = (wr * 32 + mt * 16 + g) * 20 + ks;
                af[mt][0] = Ab[rb + tig];       af[mt][1] = Ab[rb + 160 + tig];
                af[mt][2] = Ab[rb + tig + 4];   af[mt][3] = Ab[rb + 160 + tig + 4];
            }
#pragma unroll
            for (int nt = 0; nt < 8; nt++) {
                int cb = wc * 64 + nt * 8 + g;
                uint32_t b0 = Bb[(ks + tig) * 520 + cb];
                uint32_t b1 = Bb[(ks + tig + 4) * 520 + cb];
                mma_tf32(acc[0][nt], af[0], b0, b1);
                mma_tf32(acc[1][nt], af[1], b0, b1);
            }
        }
        cur = (cur + 1) & 3;
    }

#pragma unroll
    for (int mt = 0; mt < 2; mt++)
#pragma unroll
        for (int nt = 0; nt < 8; nt++) {
            int c0 = wc * 64 + nt * 8 + 2 * tig;
            int row0 = t0 + wr * 32 + mt * 16 + g;
            size_t o0 = (size_t)row0 * 512 + c0;
            size_t o1 = (size_t)(row0 + 8) * 512 + c0;
            float2 x0 = *(const float2*)&g_xn[o0];
            float2 x1 = *(const float2*)&g_xn[o1];
            *(float2*)&out[o0] = make_float2(acc[mt][nt][0] + sB[c0] + x0.x,
                                             acc[mt][nt][1] + sB[c0 + 1] + x0.y);
            *(float2*)&out[o1] = make_float2(acc[mt][nt][2] + sB[c0] + x1.x,
                                             acc[mt][nt][3] + sB[c0 + 1] + x1.y);
        }
}

// ============================================================================
extern "C" void kernel_launch(void* const* d_in, const int* in_sizes, int n_in,
                              void* d_out, int out_size)
{
    (void)in_sizes; (void)n_in; (void)out_size;
    const float* x    = (const float*)d_in[0];
    const float* ng   = (const float*)d_in[1];
    const float* nb   = (const float*)d_in[2];
    const float* hW1  = (const float*)d_in[3];
    const float* hb1  = (const float*)d_in[4];
    const float* hlg  = (const float*)d_in[5];
    const float* hlb  = (const float*)d_in[6];
    const float* hW2  = (const float*)d_in[7];
    const float* hb2  = (const float*)d_in[8];
    const float* attr = (const float*)d_in[9];
    const float* dynm = (const float*)d_in[10];
    const float* gW   = (const float*)d_in[11];
    const float* gb   = (const float*)d_in[12];
    const float* oW1  = (const float*)d_in[13];
    const float* ob1  = (const float*)d_in[14];
    const float* olg  = (const float*)d_in[15];
    const float* olb  = (const float*)d_in[16];
    const float* oW2  = (const float*)d_in[17];
    const float* ob2  = (const float*)d_in[18];
    float* out = (float*)d_out;

    cudaFuncSetAttribute(k_head1_mma, cudaFuncAttributeMaxDynamicSharedMemorySize, K2_SMEM);
    cudaFuncSetAttribute(k_head2_mma, cudaFuncAttributeMaxDynamicSharedMemorySize, K3_SMEM);
    cudaFuncSetAttribute(k_out1_mma,  cudaFuncAttributeMaxDynamicSharedMemorySize, K4_SMEM);
    cudaFuncSetAttribute(k_out2_mma,  cudaFuncAttributeMaxDynamicSharedMemorySize, K5_SMEM);

    k_prep<<<4608, 256>>>(hW1, hW2, oW1, oW2);
    k_prep2<<<547, 256>>>(hW2, dynm, attr, hb2);
    k_ln_gate<<<8192, 256>>>(x, ng, nb, gW, gb);

    dim3 gh(T_TOK / 64, 4);
    k_head1_mma<<<gh, 256, K2_SMEM>>>(hb1, hlg, hlb);
    k_head2_mma<<<gh, 256, K3_SMEM>>>(hb2, attr);

    k_out1_mma<<<T_TOK / 64, 512, K4_SMEM>>>(ob1, olg, olb);
    k_out2_mma<<<T_TOK / 64, 512, K5_SMEM>>>(ob2, out);
}